// round 1
// baseline (speedup 1.0000x reference)
#include <cuda_runtime.h>
#include <cuda_bf16.h>
#include <cstdint>

#define DIV_UP(a, b) (((a) + (b) - 1) / (b))

// Scratch for MLP ping-pong (B*Q*D = 307200 floats needed; headroom allocated)
__device__ __align__(16) float g_mlp_a[1 << 20];
__device__ __align__(16) float g_mlp_b[1 << 20];

// ---------------------------------------------------------------------------
// fp32x2 packed FMA (FFMA2): 2 FMAs per instruction on the fma pipe.
__device__ __forceinline__ void fma2(unsigned long long& c,
                                     unsigned long long a,
                                     unsigned long long b) {
    asm("fma.rn.f32x2 %0, %1, %2, %0;" : "+l"(c) : "l"(a), "l"(b));
}

__device__ __forceinline__ float2 unpack2(unsigned long long v) {
    float2 r;
    asm("mov.b64 {%0, %1}, %2;" : "=f"(r.x), "=f"(r.y) : "l"(v));
    return r;
}

// ---------------------------------------------------------------------------
// Zero-init output (it is poisoned to 0xAA by the harness).
__global__ void zero_kernel(float* __restrict__ out, long n) {
    long i = ((long)blockIdx.x * blockDim.x + threadIdx.x) * 4;
    if (i + 4 <= n) {
        *reinterpret_cast<float4*>(out + i) = make_float4(0.f, 0.f, 0.f, 0.f);
    } else if (i < n) {
        for (long j = i; j < n; ++j) out[j] = 0.f;
    }
}

// ---------------------------------------------------------------------------
// MLP layer: Y[M,N] = act(X[M,K] @ W[N,K]^T + bias). K%32==0, N%64==0 assumed.
template <int RELU>
__global__ void __launch_bounds__(256)
mlp_kernel(const float* __restrict__ X, const float* __restrict__ Wm,
           const float* __restrict__ bias, float* __restrict__ Y,
           int M, int K, int N) {
    constexpr int BM = 32, BN = 64, BK = 32;
    __shared__ __align__(16) float Xs[BK][BM + 1];
    __shared__ __align__(16) float Ws[BK][BN + 1];

    const int m0 = blockIdx.x * BM;
    const int n0 = blockIdx.y * BN;
    const int tid = threadIdx.x;
    const int ti = tid & 15;   // m direction, 2 rows each
    const int tj = tid >> 4;   // n direction, 4 cols each

    float acc[2][4] = {};

    for (int k0 = 0; k0 < K; k0 += BK) {
        // Load X tile [BM x BK] -> transposed Xs[k][m]
        {
            int r = tid >> 3, c4 = (tid & 7) * 4;
            float4 v = make_float4(0.f, 0.f, 0.f, 0.f);
            if (m0 + r < M)
                v = *reinterpret_cast<const float4*>(X + (long)(m0 + r) * K + k0 + c4);
            Xs[c4 + 0][r] = v.x; Xs[c4 + 1][r] = v.y;
            Xs[c4 + 2][r] = v.z; Xs[c4 + 3][r] = v.w;
        }
        // Load W tile [BN x BK] -> transposed Ws[k][n]
        #pragma unroll
        for (int u = 0; u < 2; ++u) {
            int idx = tid + u * 256;
            int r = idx >> 3, c4 = (idx & 7) * 4;
            float4 v = make_float4(0.f, 0.f, 0.f, 0.f);
            if (n0 + r < N)
                v = *reinterpret_cast<const float4*>(Wm + (long)(n0 + r) * K + k0 + c4);
            Ws[c4 + 0][r] = v.x; Ws[c4 + 1][r] = v.y;
            Ws[c4 + 2][r] = v.z; Ws[c4 + 3][r] = v.w;
        }
        __syncthreads();
        #pragma unroll
        for (int k = 0; k < BK; ++k) {
            float a0 = Xs[k][ti * 2 + 0];
            float a1 = Xs[k][ti * 2 + 1];
            float b0v = Ws[k][tj * 4 + 0];
            float b1v = Ws[k][tj * 4 + 1];
            float b2v = Ws[k][tj * 4 + 2];
            float b3v = Ws[k][tj * 4 + 3];
            acc[0][0] = fmaf(a0, b0v, acc[0][0]);
            acc[0][1] = fmaf(a0, b1v, acc[0][1]);
            acc[0][2] = fmaf(a0, b2v, acc[0][2]);
            acc[0][3] = fmaf(a0, b3v, acc[0][3]);
            acc[1][0] = fmaf(a1, b0v, acc[1][0]);
            acc[1][1] = fmaf(a1, b1v, acc[1][1]);
            acc[1][2] = fmaf(a1, b2v, acc[1][2]);
            acc[1][3] = fmaf(a1, b3v, acc[1][3]);
        }
        __syncthreads();
    }

    #pragma unroll
    for (int s = 0; s < 2; ++s) {
        int m = m0 + ti * 2 + s;
        if (m >= M) continue;
        #pragma unroll
        for (int jj = 0; jj < 4; ++jj) {
            int n = n0 + tj * 4 + jj;
            if (n >= N) continue;
            float v = acc[s][jj] + bias[n];
            if (RELU) v = fmaxf(v, 0.f);
            Y[(long)m * N + n] = v;
        }
    }
}

// ---------------------------------------------------------------------------
// Fused logits GEMM + scatter-add.
// For batch b: C[f,q] = fv[b*F+f,:] . qf[b*Q+q,:]; atomically added into
// out[b, h(n), w(n), q].
__global__ void __launch_bounds__(256)
logits_scatter_kernel(const float* __restrict__ fv,   // [B*F, D]
                      const int* __restrict__ fidx,   // [B*F, 3] (b, h, w)
                      const float* __restrict__ qf,   // [B*Q, D]
                      float* __restrict__ out,
                      const int* __restrict__ width_ptr, int width_imm,
                      int F, int Q, int D, long HWQ) {
    constexpr int BM = 128, BN = 64, BK = 16;
    __shared__ __align__(16) float As[BK][BM];       // A transposed: As[k][f]
    __shared__ __align__(16) float Bs[BK][2 * BN];   // B duplicated: {q,q} pairs

    const int b = blockIdx.z;
    const int f0 = blockIdx.x * BM;
    const int q0 = blockIdx.y * BN;
    const int tid = threadIdx.x;
    const int ti = tid & 15;   // f direction: 8 rows each (4 f32x2 pairs)
    const int tj = tid >> 4;   // q direction: 4 cols each

    const int Wd = width_ptr ? *width_ptr : width_imm;

    const long nbase = (long)b * F + f0;
    const float* Abase = fv + nbase * D;
    const float* Bbase = qf + (long)b * Q * D;

    unsigned long long acc[4][4] = {};  // [f-pair][q], each = 2 fp32 accums

    for (int k0 = 0; k0 < D; k0 += BK) {
        // Load A tile [BM x BK] -> transposed (f contiguous within a k-row)
        #pragma unroll
        for (int u = 0; u < 2; ++u) {
            int idx = tid + u * 256;
            int r = idx >> 2, c4 = (idx & 3) * 4;
            float4 v = make_float4(0.f, 0.f, 0.f, 0.f);
            if (f0 + r < F)
                v = *reinterpret_cast<const float4*>(Abase + (long)r * D + k0 + c4);
            As[c4 + 0][r] = v.x; As[c4 + 1][r] = v.y;
            As[c4 + 2][r] = v.z; As[c4 + 3][r] = v.w;
        }
        // Load B tile [BN x BK] -> transposed + duplicated ({q,q} in adjacent slots)
        {
            int j = tid >> 2, c4 = (tid & 3) * 4;
            float4 v = make_float4(0.f, 0.f, 0.f, 0.f);
            if (q0 + j < Q)
                v = *reinterpret_cast<const float4*>(Bbase + (long)(q0 + j) * D + k0 + c4);
            Bs[c4 + 0][2 * j] = v.x; Bs[c4 + 0][2 * j + 1] = v.x;
            Bs[c4 + 1][2 * j] = v.y; Bs[c4 + 1][2 * j + 1] = v.y;
            Bs[c4 + 2][2 * j] = v.z; Bs[c4 + 2][2 * j + 1] = v.z;
            Bs[c4 + 3][2 * j] = v.w; Bs[c4 + 3][2 * j + 1] = v.w;
        }
        __syncthreads();

        #pragma unroll
        for (int k = 0; k < BK; ++k) {
            ulonglong2 a01 = *reinterpret_cast<const ulonglong2*>(&As[k][ti * 8]);
            ulonglong2 a23 = *reinterpret_cast<const ulonglong2*>(&As[k][ti * 8 + 4]);
            ulonglong2 b01 = *reinterpret_cast<const ulonglong2*>(&Bs[k][tj * 8]);
            ulonglong2 b23 = *reinterpret_cast<const ulonglong2*>(&Bs[k][tj * 8 + 4]);
            unsigned long long ap[4] = {a01.x, a01.y, a23.x, a23.y};
            unsigned long long bd[4] = {b01.x, b01.y, b23.x, b23.y};
            #pragma unroll
            for (int p = 0; p < 4; ++p) {
                #pragma unroll
                for (int j = 0; j < 4; ++j) fma2(acc[p][j], ap[p], bd[j]);
            }
        }
        __syncthreads();
    }

    // Epilogue: atomic scatter-add into out[b, h, w, qbase..]
    const int qbase = q0 + tj * 4;
    int qcnt = Q - qbase;
    if (qcnt <= 0) return;
    if (qcnt > 4) qcnt = 4;

    #pragma unroll
    for (int p = 0; p < 4; ++p) {
        float2 r0 = unpack2(acc[p][0]);
        float2 r1 = unpack2(acc[p][1]);
        float2 r2 = unpack2(acc[p][2]);
        float2 r3 = unpack2(acc[p][3]);
        int fi = ti * 8 + p * 2;
        if (f0 + fi >= F) continue;
        long n = nbase + fi;
        {   // even f row
            int h = fidx[3 * n + 1], w = fidx[3 * n + 2];
            long base = (long)b * HWQ + ((long)h * Wd + w) * (long)Q + qbase;
            float v[4] = {r0.x, r1.x, r2.x, r3.x};
            for (int jj = 0; jj < qcnt; ++jj) atomicAdd(out + base + jj, v[jj]);
        }
        if (f0 + fi + 1 < F) {   // odd f row
            long n1 = n + 1;
            int h = fidx[3 * n1 + 1], w = fidx[3 * n1 + 2];
            long base = (long)b * HWQ + ((long)h * Wd + w) * (long)Q + qbase;
            float v[4] = {r0.y, r1.y, r2.y, r3.y};
            for (int jj = 0; jj < qcnt; ++jj) atomicAdd(out + base + jj, v[jj]);
        }
    }
}

// ---------------------------------------------------------------------------
static int isqrt_host(long v) {
    int r = (int)(sqrt((double)v) + 0.5);
    while ((long)r * r > v) --r;
    while ((long)(r + 1) * (r + 1) <= v) ++r;
    return r;
}

extern "C" void kernel_launch(void* const* d_in, const int* in_sizes, int n_in,
                              void* d_out, int out_size) {
    // Input layout (metadata order): queries, feature_values, feature_indices,
    // query_batch_offsets, feature_batch_offsets, height, width, W0,b0,...,W3,b3.
    const float* queries = (const float*)d_in[0];
    const float* fv      = (const float*)d_in[1];
    const int*   fidx    = (const int*)d_in[2];

    bool scalars_present = (n_in >= 15 && in_sizes[5] == 1 && in_sizes[6] == 1);
    int wbase = scalars_present ? 7 : 5;
    const int* width_ptr = scalars_present ? (const int*)d_in[6] : nullptr;

    const float* Wl[4];
    const float* bl[4];
    for (int i = 0; i < 4; ++i) {
        Wl[i] = (const float*)d_in[wbase + 2 * i];
        bl[i] = (const float*)d_in[wbase + 2 * i + 1];
    }

    const int D  = in_sizes[wbase + 1];       // len(b0)
    const int Mq = in_sizes[0] / D;           // B*Q
    const int B  = in_sizes[3] - 1;
    const int Q  = Mq / B;
    const int NF = in_sizes[1] / D;           // B*F
    const int F  = NF / B;
    const long HWQ = (long)out_size / B;      // H*W*Q
    const int width_imm = isqrt_host(HWQ / Q);  // fallback, assumes H==W

    float* buf0 = nullptr;
    float* buf1 = nullptr;
    cudaGetSymbolAddress((void**)&buf0, g_mlp_a);
    cudaGetSymbolAddress((void**)&buf1, g_mlp_b);

    // 1) Zero the output
    {
        long n = out_size;
        int blocks = (int)DIV_UP(n, (long)256 * 4);
        zero_kernel<<<blocks, 256>>>((float*)d_out, n);
    }

    // 2) Query MLP: 3x (linear+relu), 1x linear
    {
        dim3 grid(DIV_UP(Mq, 32), DIV_UP(D, 64));
        mlp_kernel<1><<<grid, 256>>>(queries, Wl[0], bl[0], buf0, Mq, D, D);
        mlp_kernel<1><<<grid, 256>>>(buf0,    Wl[1], bl[1], buf1, Mq, D, D);
        mlp_kernel<1><<<grid, 256>>>(buf1,    Wl[2], bl[2], buf0, Mq, D, D);
        mlp_kernel<0><<<grid, 256>>>(buf0,    Wl[3], bl[3], buf1, Mq, D, D);
    }

    // 3) Logits GEMM fused with scatter-add
    {
        dim3 grid(DIV_UP(F, 128), DIV_UP(Q, 64), B);
        logits_scatter_kernel<<<grid, 256>>>(fv, fidx, buf1, (float*)d_out,
                                             width_ptr, width_imm,
                                             F, Q, D, HWQ);
    }
}

// round 3
// speedup vs baseline: 2.6877x; 2.6877x over previous
#include <cuda_runtime.h>
#include <cuda_bf16.h>
#include <cstdint>
#include <cmath>

#define DIV_UP(a, b) (((a) + (b) - 1) / (b))

// Scratch for MLP ping-pong (B*Q*D = 307200 floats needed; headroom allocated)
__device__ __align__(16) float g_mlp_a[1 << 20];
__device__ __align__(16) float g_mlp_b[1 << 20];

// ============================================================================
// helpers
// ============================================================================
__device__ __forceinline__ uint32_t smem_to_u32(const void* smem_ptr) {
    uint32_t addr;
    asm("{ .reg .u64 tmp; cvta.to.shared.u64 tmp, %1; cvt.u32.u64 %0, tmp; }"
        : "=r"(addr) : "l"(smem_ptr));
    return addr;
}

__device__ __forceinline__ void ldmatrix_x4(uint32_t* r, uint32_t addr) {
    asm volatile("ldmatrix.sync.aligned.m8n8.x4.shared.b16 {%0,%1,%2,%3}, [%4];"
                 : "=r"(r[0]), "=r"(r[1]), "=r"(r[2]), "=r"(r[3]) : "r"(addr));
}

// D = A(bf16) * B(bf16)^T + D, m16n8k16
__device__ __forceinline__ void mma_bf16(float* c, const uint32_t* a,
                                         const uint32_t* b) {
    asm volatile(
        "mma.sync.aligned.m16n8k16.row.col.f32.bf16.bf16.f32 "
        "{%0,%1,%2,%3}, {%4,%5,%6,%7}, {%8,%9}, {%0,%1,%2,%3};"
        : "+f"(c[0]), "+f"(c[1]), "+f"(c[2]), "+f"(c[3])
        : "r"(a[0]), "r"(a[1]), "r"(a[2]), "r"(a[3]), "r"(b[0]), "r"(b[1]));
}

// split fp32 pair into packed bf16x2 hi and lo planes
__device__ __forceinline__ void split2(float x, float y, uint32_t& hi, uint32_t& lo) {
    __nv_bfloat16 hx = __float2bfloat16(x);
    __nv_bfloat16 hy = __float2bfloat16(y);
    __nv_bfloat16 lx = __float2bfloat16(x - __bfloat162float(hx));
    __nv_bfloat16 ly = __float2bfloat16(y - __bfloat162float(hy));
    hi = (uint32_t)__bfloat16_as_ushort(hx) | ((uint32_t)__bfloat16_as_ushort(hy) << 16);
    lo = (uint32_t)__bfloat16_as_ushort(lx) | ((uint32_t)__bfloat16_as_ushort(ly) << 16);
}

// ============================================================================
// MLP layer: Y[M,N] = act(X[M,K] @ W[N,K]^T + bias). 32x32 tiles.
// ============================================================================
template <int RELU>
__global__ void __launch_bounds__(256)
mlp_kernel(const float* __restrict__ X, const float* __restrict__ Wm,
           const float* __restrict__ bias, float* __restrict__ Y,
           int M, int K, int N) {
    constexpr int BM = 32, BN = 32, BK = 32;
    __shared__ __align__(16) float Xs[BK][BM + 1];
    __shared__ __align__(16) float Ws[BK][BN + 1];

    const int m0 = blockIdx.x * BM;
    const int n0 = blockIdx.y * BN;
    const int tid = threadIdx.x;
    const int ti = tid & 15;
    const int tj = tid >> 4;

    float acc[2][2] = {};

    for (int k0 = 0; k0 < K; k0 += BK) {
        {
            int r = tid >> 3, c4 = (tid & 7) * 4;
            float4 v = make_float4(0.f, 0.f, 0.f, 0.f);
            if (m0 + r < M)
                v = *reinterpret_cast<const float4*>(X + (long)(m0 + r) * K + k0 + c4);
            Xs[c4 + 0][r] = v.x; Xs[c4 + 1][r] = v.y;
            Xs[c4 + 2][r] = v.z; Xs[c4 + 3][r] = v.w;
        }
        {
            int r = tid >> 3, c4 = (tid & 7) * 4;
            float4 v = make_float4(0.f, 0.f, 0.f, 0.f);
            if (n0 + r < N)
                v = *reinterpret_cast<const float4*>(Wm + (long)(n0 + r) * K + k0 + c4);
            Ws[c4 + 0][r] = v.x; Ws[c4 + 1][r] = v.y;
            Ws[c4 + 2][r] = v.z; Ws[c4 + 3][r] = v.w;
        }
        __syncthreads();
        #pragma unroll
        for (int k = 0; k < BK; ++k) {
            float a0 = Xs[k][ti * 2 + 0];
            float a1 = Xs[k][ti * 2 + 1];
            float b0 = Ws[k][tj * 2 + 0];
            float b1 = Ws[k][tj * 2 + 1];
            acc[0][0] = fmaf(a0, b0, acc[0][0]);
            acc[0][1] = fmaf(a0, b1, acc[0][1]);
            acc[1][0] = fmaf(a1, b0, acc[1][0]);
            acc[1][1] = fmaf(a1, b1, acc[1][1]);
        }
        __syncthreads();
    }

    #pragma unroll
    for (int s = 0; s < 2; ++s) {
        int m = m0 + ti * 2 + s;
        if (m >= M) continue;
        #pragma unroll
        for (int j = 0; j < 2; ++j) {
            int n = n0 + tj * 2 + j;
            if (n >= N) continue;
            float v = acc[s][j] + bias[n];
            if (RELU) v = fmaxf(v, 0.f);
            Y[(long)m * N + n] = v;
        }
    }
}

// ============================================================================
// Logits GEMM via mma.sync bf16 (hi/lo split) + fused float2 atomic scatter.
// CTA tile: 128(f) x 64(q). 8 warps as 4(m) x 2(n); warp tile 32x32.
// K chunked by 32 (2 mma k-steps per chunk).
// ============================================================================
constexpr int FTILE = 128;
constexpr int QTILE = 64;
constexpr int KC    = 32;
constexpr int LDSA  = KC + 8;   // bf16 elements per row (padding kills conflicts)

__global__ void __launch_bounds__(256)
logits_mma_kernel(const float* __restrict__ fv,   // [B*F, D]
                  const int* __restrict__ fidx,   // [B*F, 3]
                  const float* __restrict__ qf,   // [B*Q, D]
                  float* __restrict__ out,
                  const int* __restrict__ width_ptr, int width_imm,
                  int F, int Q, int D, long HWQ) {
    __shared__ __align__(16) __nv_bfloat16 As_hi[FTILE * LDSA];
    __shared__ __align__(16) __nv_bfloat16 As_lo[FTILE * LDSA];
    __shared__ __align__(16) __nv_bfloat16 Bs_hi[QTILE * LDSA];
    __shared__ __align__(16) __nv_bfloat16 Bs_lo[QTILE * LDSA];

    const int tid  = threadIdx.x;
    const int wid  = tid >> 5;
    const int lane = tid & 31;
    const int b  = blockIdx.z;
    const int f0 = blockIdx.x * FTILE;
    const int q0 = blockIdx.y * QTILE;

    const int warp_m = (wid & 3) * 32;
    const int warp_n = (wid >> 2) * 32;

    const float* Abase = fv + ((long)b * F + f0) * D;
    const float* Bbase = qf + ((long)b * Q) * D;

    float c[2][4][4] = {};   // [m-frag 16][n-frag 8][regs]

    const uint32_t as_hi = smem_to_u32(As_hi);
    const uint32_t as_lo = smem_to_u32(As_lo);
    const uint32_t bs_hi = smem_to_u32(Bs_hi);
    const uint32_t bs_lo = smem_to_u32(Bs_lo);

    for (int k0 = 0; k0 < D; k0 += KC) {
        // ---- load + split A tile: 128 x 32 fp32 (1024 float4, 4/thread) ----
        #pragma unroll
        for (int i = 0; i < 4; ++i) {
            int quad = tid + i * 256;
            int row = quad >> 3;            // 0..127
            int c4  = (quad & 7) << 2;      // 0..28
            float4 v = make_float4(0.f, 0.f, 0.f, 0.f);
            if (f0 + row < F)
                v = *reinterpret_cast<const float4*>(Abase + (long)row * D + k0 + c4);
            uint32_t h0, l0, h1, l1;
            split2(v.x, v.y, h0, l0);
            split2(v.z, v.w, h1, l1);
            int off = row * LDSA + c4;
            *reinterpret_cast<uint2*>(&As_hi[off]) = make_uint2(h0, h1);
            *reinterpret_cast<uint2*>(&As_lo[off]) = make_uint2(l0, l1);
        }
        // ---- load + split B tile: 64 x 32 fp32 (512 float4, 2/thread) ----
        #pragma unroll
        for (int i = 0; i < 2; ++i) {
            int quad = tid + i * 256;
            int row = quad >> 3;            // 0..63
            int c4  = (quad & 7) << 2;
            float4 v = make_float4(0.f, 0.f, 0.f, 0.f);
            if (q0 + row < Q)
                v = *reinterpret_cast<const float4*>(Bbase + (long)(q0 + row) * D + k0 + c4);
            uint32_t h0, l0, h1, l1;
            split2(v.x, v.y, h0, l0);
            split2(v.z, v.w, h1, l1);
            int off = row * LDSA + c4;
            *reinterpret_cast<uint2*>(&Bs_hi[off]) = make_uint2(h0, h1);
            *reinterpret_cast<uint2*>(&Bs_lo[off]) = make_uint2(l0, l1);
        }
        __syncthreads();

        // ---- mainloop: 2 k16 steps ----
        #pragma unroll
        for (int kk = 0; kk < KC; kk += 16) {
            uint32_t ah[2][4], al[2][4];
            #pragma unroll
            for (int mi = 0; mi < 2; ++mi) {
                int row = warp_m + mi * 16 + (lane & 15);
                int col = kk + ((lane >> 4) << 3);
                uint32_t addr = (uint32_t)((row * LDSA + col) * 2);
                ldmatrix_x4(ah[mi], as_hi + addr);
                ldmatrix_x4(al[mi], as_lo + addr);
            }
            uint32_t bh[4][2], bl[4][2];
            #pragma unroll
            for (int nb = 0; nb < 2; ++nb) {
                // lanes 0-7: n rows 0-7 @k0 | 8-15: same rows @k8
                // lanes 16-23: n rows 8-15 @k0 | 24-31: @k8
                int row = warp_n + nb * 16 + ((lane & 16) >> 1) + (lane & 7);
                int col = kk + ((lane >> 3) & 1) * 8;
                uint32_t addr = (uint32_t)((row * LDSA + col) * 2);
                uint32_t rh[4], rl[4];
                ldmatrix_x4(rh, bs_hi + addr);
                ldmatrix_x4(rl, bs_lo + addr);
                bh[nb * 2 + 0][0] = rh[0]; bh[nb * 2 + 0][1] = rh[1];
                bh[nb * 2 + 1][0] = rh[2]; bh[nb * 2 + 1][1] = rh[3];
                bl[nb * 2 + 0][0] = rl[0]; bl[nb * 2 + 0][1] = rl[1];
                bl[nb * 2 + 1][0] = rl[2]; bl[nb * 2 + 1][1] = rl[3];
            }
            #pragma unroll
            for (int mi = 0; mi < 2; ++mi) {
                #pragma unroll
                for (int ni = 0; ni < 4; ++ni) {
                    mma_bf16(c[mi][ni], ah[mi], bh[ni]);   // hi*hi
                    mma_bf16(c[mi][ni], ah[mi], bl[ni]);   // hi*lo
                    mma_bf16(c[mi][ni], al[mi], bh[ni]);   // lo*hi
                }
            }
        }
        __syncthreads();
    }

    // ---- epilogue: scatter-add with float2 atomics ----
    const int Wd = width_ptr ? *width_ptr : width_imm;
    const long nb0 = (long)b * F + f0;

    #pragma unroll
    for (int mi = 0; mi < 2; ++mi) {
        #pragma unroll
        for (int half = 0; half < 2; ++half) {   // +0 / +8 rows within m16
            int row = warp_m + mi * 16 + half * 8 + (lane >> 2);
            int f = f0 + row;
            if (f >= F) continue;
            long n = nb0 + row;
            int hh = fidx[3 * n + 1];
            int ww = fidx[3 * n + 2];
            long obase = (long)b * HWQ + ((long)hh * Wd + ww) * (long)Q;
            #pragma unroll
            for (int ni = 0; ni < 4; ++ni) {
                int q = q0 + warp_n + ni * 8 + 2 * (lane & 3);
                float v0 = c[mi][ni][half * 2 + 0];
                float v1 = c[mi][ni][half * 2 + 1];
                if (q + 1 < Q) {
                    atomicAdd(reinterpret_cast<float2*>(out + obase + q),
                              make_float2(v0, v1));
                } else if (q < Q) {
                    atomicAdd(out + obase + q, v0);
                }
            }
        }
    }
}

// ---------------------------------------------------------------------------
static int isqrt_host(long v) {
    int r = (int)(sqrt((double)v) + 0.5);
    while ((long)r * r > v) --r;
    while ((long)(r + 1) * (r + 1) <= v) ++r;
    return r;
}

extern "C" void kernel_launch(void* const* d_in, const int* in_sizes, int n_in,
                              void* d_out, int out_size) {
    // Input order: queries, feature_values, feature_indices, query_batch_offsets,
    // feature_batch_offsets, height, width, W0,b0, W1,b1, W2,b2, W3,b3.
    const float* queries = (const float*)d_in[0];
    const float* fv      = (const float*)d_in[1];
    const int*   fidx    = (const int*)d_in[2];

    bool scalars_present = (n_in >= 15 && in_sizes[5] == 1 && in_sizes[6] == 1);
    int wbase = scalars_present ? 7 : 5;
    const int* width_ptr = scalars_present ? (const int*)d_in[6] : nullptr;

    const float* Wl[4];
    const float* bl[4];
    for (int i = 0; i < 4; ++i) {
        Wl[i] = (const float*)d_in[wbase + 2 * i];
        bl[i] = (const float*)d_in[wbase + 2 * i + 1];
    }

    const int D  = in_sizes[wbase + 1];       // len(b0)
    const int Mq = in_sizes[0] / D;           // B*Q
    const int B  = in_sizes[3] - 1;
    const int Q  = Mq / B;
    const int NF = in_sizes[1] / D;           // B*F
    const int F  = NF / B;
    const long HWQ = (long)out_size / B;      // H*W*Q
    const int width_imm = isqrt_host(HWQ / Q);

    float* buf0 = nullptr;
    float* buf1 = nullptr;
    cudaGetSymbolAddress((void**)&buf0, g_mlp_a);
    cudaGetSymbolAddress((void**)&buf1, g_mlp_b);

    // 1) Zero the output (poisoned by harness)
    cudaMemsetAsync(d_out, 0, (size_t)out_size * sizeof(float), 0);

    // 2) Query MLP: 3x (linear+relu), 1x linear
    {
        dim3 grid(DIV_UP(Mq, 32), DIV_UP(D, 32));
        mlp_kernel<1><<<grid, 256>>>(queries, Wl[0], bl[0], buf0, Mq, D, D);
        mlp_kernel<1><<<grid, 256>>>(buf0,    Wl[1], bl[1], buf1, Mq, D, D);
        mlp_kernel<1><<<grid, 256>>>(buf1,    Wl[2], bl[2], buf0, Mq, D, D);
        mlp_kernel<0><<<grid, 256>>>(buf0,    Wl[3], bl[3], buf1, Mq, D, D);
    }

    // 3) Logits GEMM (mma.sync bf16 split) fused with scatter-add
    {
        dim3 grid(DIV_UP(F, FTILE), DIV_UP(Q, QTILE), B);
        logits_mma_kernel<<<grid, 256>>>(fv, fidx, buf1, (float*)d_out,
                                         width_ptr, width_imm,
                                         F, Q, D, HWQ);
    }
}